// round 7
// baseline (speedup 1.0000x reference)
#include <cuda_runtime.h>
#include <math.h>

#define B 64
#define NTOK 4096
#define D 64
#define S 8
#define HID 128
#define CHUNKS 16
#define NC (NTOK / CHUNKS)   /* 256 tokens per block */
#define TILE 128
#define TPB 128
#define XS_STRIDE 68         /* floats per token row; 272B, 16B aligned */

typedef unsigned long long u64t;

__device__ __forceinline__ u64t f2_fma(u64t a, u64t b, u64t c) {
    u64t d;
    asm("fma.rn.f32x2 %0, %1, %2, %3;" : "=l"(d) : "l"(a), "l"(b), "l"(c));
    return d;
}
__device__ __forceinline__ u64t f2_add(u64t a, u64t b) {
    u64t d;
    asm("add.rn.f32x2 %0, %1, %2;" : "=l"(d) : "l"(a), "l"(b));
    return d;
}
__device__ __forceinline__ float2 f2_unpack(u64t a) {
    float2 r;
    asm("mov.b64 {%0, %1}, %2;" : "=f"(r.x), "=f"(r.y) : "l"(a));
    return r;
}

// ---------------- device scratch ----------------
__device__ float g_slots[B * S * D];
__device__ float g_qhat[B * S * D];
__device__ float g_sq[B * S];
__device__ float g_cst[B * S];
__device__ float g_P[B * CHUNKS * S * D];
__device__ float g_Td[B * CHUNKS * 16];
__device__ float g_wqk[D * D];
__device__ float g_bqk[D];
__device__ float g_wqbk[D];
__device__ float g_bqbk[1];
__device__ int g_cnt[B];

// ---------------- precompute folded weight products ----------------
__global__ __launch_bounds__(256) void k_pre(const float* __restrict__ wq,
                                             const float* __restrict__ bq,
                                             const float* __restrict__ wk,
                                             const float* __restrict__ bk) {
    int t = threadIdx.x;
    for (int o = t; o < D * D; o += 256) {
        int e = o >> 6, e2 = o & 63;
        float s = 0.f;
        for (int d = 0; d < D; d++) s += wq[e * D + d] * wk[e2 * D + d];
        g_wqk[o] = s;
    }
    for (int e2 = t; e2 < D; e2 += 256) {
        float s = 0.f;
        for (int d = 0; d < D; d++) s += bq[d] * wk[e2 * D + d];
        g_bqk[e2] = s;
    }
    for (int e = t; e < D; e += 256) {
        float s = 0.f;
        for (int d = 0; d < D; d++) s += wq[e * D + d] * bk[d];
        g_wqbk[e] = s;
    }
    if (t == 0) {
        float s = 0.f;
        for (int d = 0; d < D; d++) s += bq[d] * bk[d];
        g_bqbk[0] = s;
    }
}

// ---------------- q-fold (init path) ----------------
__device__ void compute_q_from_slots(int b, const float* s_slots,
                                     const float* __restrict__ g_sl,
                                     const float* __restrict__ be_sl,
                                     const float* __restrict__ g_in,
                                     const float* __restrict__ be_in,
                                     float* s_sln, float* s_tmp) {
    int tid = threadIdx.x;
    int w = tid >> 5, lane = tid & 31;
    {
        float v0 = s_slots[w * 64 + lane];
        float v1 = s_slots[w * 64 + 32 + lane];
        float s = v0 + v1, s2 = v0 * v0 + v1 * v1;
#pragma unroll
        for (int off = 16; off; off >>= 1) {
            s += __shfl_xor_sync(0xffffffffu, s, off);
            s2 += __shfl_xor_sync(0xffffffffu, s2, off);
        }
        float m = s * (1.f / 64.f);
        float var = s2 * (1.f / 64.f) - m * m;
        float r = rsqrtf(var + 1e-5f);
        s_sln[w * 64 + lane] = (v0 - m) * r * g_sl[lane] + be_sl[lane];
        s_sln[w * 64 + 32 + lane] = (v1 - m) * r * g_sl[lane + 32] + be_sl[lane + 32];
    }
    __syncthreads();
    for (int rep = 0; rep < 2; rep++) {
        int idx = tid + rep * 256;
        int i = idx >> 6, e2 = idx & 63;
        float acc = g_bqk[e2];
#pragma unroll 8
        for (int e = 0; e < 64; e++) acc += s_sln[i * 64 + e] * g_wqk[e * 64 + e2];
        float qt = 0.125f * acc;
        float qh = qt * g_in[e2];
        g_qhat[b * S * D + idx] = qh;
        s_tmp[idx] = qh;
        s_tmp[512 + idx] = qt * be_in[e2];
    }
    __syncthreads();
    if (tid < S) {
        float sq = 0.f, cb = 0.f;
        for (int e2 = 0; e2 < 64; e2++) {
            sq += s_tmp[tid * 64 + e2];
            cb += s_tmp[512 + tid * 64 + e2];
        }
        float qb = g_bqbk[0];
        for (int e = 0; e < 64; e++) qb += s_sln[tid * 64 + e] * g_wqbk[e];
        g_sq[b * S + tid] = sq;
        g_cst[b * S + tid] = cb + 0.125f * qb;
    }
}

// ---------------- init ----------------
__global__ __launch_bounds__(256) void k_init(const float* __restrict__ noise,
                                              const float* __restrict__ mu,
                                              const float* __restrict__ ls,
                                              const float* __restrict__ g_sl,
                                              const float* __restrict__ be_sl,
                                              const float* __restrict__ g_in,
                                              const float* __restrict__ be_in) {
    __shared__ float s_slots[512];
    __shared__ float s_sln[512];
    __shared__ float s_tmp[1024];
    int b = blockIdx.x, tid = threadIdx.x;
    if (tid == 0) g_cnt[b] = 0;
    for (int k = tid; k < 512; k += 256) {
        int d = k & 63;
        float v = mu[d] + expf(ls[d]) * noise[b * 512 + k];
        s_slots[k] = v;
        g_slots[b * 512 + k] = v;
    }
    __syncthreads();
    compute_q_from_slots(b, s_slots, g_sl, be_sl, g_in, be_in, s_sln, s_tmp);
}

// ================= fused main + epilogue =================
// pool layout (floats):
//   main: [0,8704) xs  [8704,10752) attn2 (splatted pairs)  [10752,11264) qh
//         [11264,11272) sqs  [11272,11280) csts  [11280,11344) s_red(4x16)
//   epi:  e_prev 0  e_num 512  e_upd 1024  e_new 1536  e_ff 2048
//         e_h1 2560(1024)  e_gx 3584(1536)  e_gh 5120(1536)
//         e_pp 6656(512)   e_Td 7168(16)
#define POOL_FLOATS 11344

__global__ __launch_bounds__(TPB, 4) void k_main(
    const float* __restrict__ x,
    const float* __restrict__ wv, const float* __restrict__ bv,
    const float* __restrict__ w_ih, const float* __restrict__ b_ih,
    const float* __restrict__ w_hh, const float* __restrict__ b_hh,
    const float* __restrict__ w1, const float* __restrict__ b1,
    const float* __restrict__ w2, const float* __restrict__ b2,
    const float* __restrict__ g_ff, const float* __restrict__ be_ff,
    const float* __restrict__ g_sl, const float* __restrict__ be_sl,
    const float* __restrict__ g_in, const float* __restrict__ be_in,
    float* __restrict__ out, int last) {
    __shared__ __align__(16) float pool[POOL_FLOATS];
    __shared__ int s_fin;

    float* xs = pool;
    float* attn2 = pool + 8704;
    float* qh = pool + 10752;
    float* sqs = pool + 11264;
    float* csts = pool + 11272;
    float* s_red = pool + 11280;   // 4 warps x 16

    int b = blockIdx.y, c = blockIdx.x, tid = threadIdx.x;

    for (int k = tid; k < S * D; k += TPB) qh[k] = g_qhat[b * S * D + k];
    if (tid < S) {
        sqs[tid] = g_sq[b * S + tid];
        csts[tid] = g_cst[b * S + tid];
    }

    // phase-2 ownership: warp g = tid>>5 owns slots {g, g+4}; lane dp = dims (2dp,2dp+1)
    const int g = tid >> 5, dp = tid & 31;
    u64t accA = 0ULL, accB = 0ULL;
    float Tl[S], dl[S];
#pragma unroll
    for (int i = 0; i < S; i++) { Tl[i] = 0.f; dl[i] = 0.f; }

    const float* xb = x + ((size_t)b * NTOK + (size_t)c * NC) * D;

    for (int t = 0; t < NC / TILE; t++) {
        __syncthreads();
        const float4* src = (const float4*)(xb + t * TILE * D);
#pragma unroll
        for (int k = 0; k < 16; k++) {
            int idx = tid + k * TPB;
            float4 v = src[idx];
            float* dst = &xs[(idx >> 4) * XS_STRIDE + (idx & 15) * 4];
            dst[0] = v.x; dst[1] = v.y; dst[2] = v.z; dst[3] = v.w;
        }
        __syncthreads();

        // ---- phase 1: thread owns token j = tid
        u64t dslP[S];
#pragma unroll
        for (int i = 0; i < S; i++) dslP[i] = 0ULL;
        u64t sA = 0ULL, sB = 0ULL, qA = 0ULL, qB = 0ULL;
        const ulonglong2* xr2 = (const ulonglong2*)&xs[tid * XS_STRIDE];
        const ulonglong2* qh2 = (const ulonglong2*)qh;
#pragma unroll
        for (int d4 = 0; d4 < 16; d4++) {
            ulonglong2 xp = xr2[d4];
            sA = f2_add(sA, xp.x);
            sB = f2_add(sB, xp.y);
            qA = f2_fma(xp.x, xp.x, qA);
            qB = f2_fma(xp.y, xp.y, qB);
#pragma unroll
            for (int i = 0; i < S; i++) {
                ulonglong2 qp = qh2[i * 16 + d4];
                dslP[i] = f2_fma(qp.x, xp.x, dslP[i]);
                dslP[i] = f2_fma(qp.y, xp.y, dslP[i]);
            }
        }
        float2 sfin = f2_unpack(f2_add(sA, sB));
        float2 qfin = f2_unpack(f2_add(qA, qB));
        float sum = sfin.x + sfin.y;
        float s2 = qfin.x + qfin.y;

        float m = sum * (1.f / 64.f);
        float var = s2 * (1.f / 64.f) - m * m;
        float r = rsqrtf(var + 1e-5f);
        float mx = -1e30f, dots[S];
#pragma unroll
        for (int i = 0; i < S; i++) {
            float2 dpv = f2_unpack(dslP[i]);
            float dsl = dpv.x + dpv.y;
            dots[i] = r * (dsl - m * sqs[i]) + csts[i];
            mx = fmaxf(mx, dots[i]);
        }
        float es = 0.f, ex[S];
#pragma unroll
        for (int i = 0; i < S; i++) { ex[i] = __expf(dots[i] - mx); es += ex[i]; }
        float inv = 1.f / es;
        float rm = r * m;
#pragma unroll
        for (int i = 0; i < S; i++) {
            float ai = ex[i] * inv + 1e-8f;
            dl[i] += ai;
            Tl[i] += ai * rm;
            float ar = ai * r;
            *(float2*)&attn2[i * (2 * TILE) + tid * 2] = make_float2(ar, ar);  // splatted
        }
        __syncthreads();

        // ---- phase 2: packed f32x2, token pairs
        const float4* aA = (const float4*)&attn2[g * (2 * TILE)];
        const float4* aB = (const float4*)&attn2[(g + 4) * (2 * TILE)];
#pragma unroll 4
        for (int j2 = 0; j2 < TILE / 2; j2++) {
            u64t xj = *(const u64t*)&xs[(2 * j2) * XS_STRIDE + 2 * dp];
            u64t xj1 = *(const u64t*)&xs[(2 * j2 + 1) * XS_STRIDE + 2 * dp];
            float4 fa = aA[j2];           // (a_j, a_j, a_j1, a_j1) broadcast
            float4 fb = aB[j2];
            u64t la = *(const u64t*)&fa.x, ha = *(const u64t*)&fa.z;
            u64t lb = *(const u64t*)&fb.x, hb = *(const u64t*)&fb.z;
            accA = f2_fma(xj, la, accA);
            accA = f2_fma(xj1, ha, accA);
            accB = f2_fma(xj, lb, accB);
            accB = f2_fma(xj1, hb, accB);
        }
    }

    // ---- write P / Td partials
    {
        float2 pa = f2_unpack(accA);
        float2 pb = f2_unpack(accB);
        float* Pp = &g_P[(b * CHUNKS + c) * S * D];
        Pp[g * D + 2 * dp] = pa.x;
        Pp[g * D + 2 * dp + 1] = pa.y;
        Pp[(g + 4) * D + 2 * dp] = pb.x;
        Pp[(g + 4) * D + 2 * dp + 1] = pb.y;
    }
#pragma unroll
    for (int i = 0; i < S; i++) {
#pragma unroll
        for (int off = 16; off; off >>= 1) {
            Tl[i] += __shfl_xor_sync(0xffffffffu, Tl[i], off);
            dl[i] += __shfl_xor_sync(0xffffffffu, dl[i], off);
        }
    }
    if (dp == 0) {
#pragma unroll
        for (int i = 0; i < S; i++) { s_red[g * 16 + i] = Tl[i]; s_red[g * 16 + 8 + i] = dl[i]; }
    }
    __syncthreads();
    if (tid < 16) {
        float s = s_red[tid] + s_red[16 + tid] + s_red[32 + tid] + s_red[48 + tid];
        g_Td[(b * CHUNKS + c) * 16 + tid] = s;
    }

    // ---- last-block ticket
    __threadfence();
    __syncthreads();
    if (tid == 0) {
        int old = atomicAdd(&g_cnt[b], 1);
        s_fin = (old == CHUNKS - 1) ? 1 : 0;
        if (s_fin) g_cnt[b] = 0;
    }
    __syncthreads();
    if (!s_fin) return;
    __threadfence();

    // ================= epilogue (finisher block, 128 threads) =================
    float* e_prev = pool;
    float* e_num = pool + 512;
    float* e_upd = pool + 1024;
    float* e_new = pool + 1536;
    float* e_ff = pool + 2048;
    float* e_h1 = pool + 2560;
    float* e_gx = pool + 3584;
    float* e_gh = pool + 5120;
    float* e_pp = pool + 6656;
    float* e_Td = pool + 7168;

    // ---- A: Td, prev, P-reduce, numer
    if (tid < 16) {
        float s = 0.f;
#pragma unroll
        for (int c2 = 0; c2 < CHUNKS; c2++) s += g_Td[(b * CHUNKS + c2) * 16 + tid];
        e_Td[tid] = s;
    }
#pragma unroll
    for (int rep = 0; rep < 4; rep++) {
        int k = tid + rep * TPB;
        e_prev[k] = g_slots[b * 512 + k];
        float P = 0.f;
#pragma unroll
        for (int c2 = 0; c2 < CHUNKS; c2++) P += g_P[(b * CHUNKS + c2) * 512 + k];
        e_pp[k] = P;
    }
    __syncthreads();
#pragma unroll
    for (int rep = 0; rep < 4; rep++) {
        int k = tid + rep * TPB;
        int i = k >> 6, d = k & 63;
        e_num[k] = g_in[d] * (e_pp[k] - e_Td[i]) + e_Td[8 + i] * be_in[d];
    }
    __syncthreads();

    // ---- B: upd = (num @ wv)/den + bv  (d = tid&63; group owns 4 slots)
    {
        int d = tid & 63, grp = tid >> 6;
        float a0 = 0.f, a1 = 0.f, a2 = 0.f, a3 = 0.f;
#pragma unroll 8
        for (int e = 0; e < 64; e++) {
            float w = wv[e * 64 + d];
            a0 += e_num[(4 * grp + 0) * 64 + e] * w;
            a1 += e_num[(4 * grp + 1) * 64 + e] * w;
            a2 += e_num[(4 * grp + 2) * 64 + e] * w;
            a3 += e_num[(4 * grp + 3) * 64 + e] * w;
        }
        e_upd[(4 * grp + 0) * 64 + d] = a0 / e_Td[8 + 4 * grp + 0] + bv[d];
        e_upd[(4 * grp + 1) * 64 + d] = a1 / e_Td[8 + 4 * grp + 1] + bv[d];
        e_upd[(4 * grp + 2) * 64 + d] = a2 / e_Td[8 + 4 * grp + 2] + bv[d];
        e_upd[(4 * grp + 3) * 64 + d] = a3 / e_Td[8 + 4 * grp + 3] + bv[d];
    }
    __syncthreads();

    // ---- C: GRU gates (o strided by 128; 8 slot accs)
    for (int o = tid; o < 192; o += TPB) {
        float gx[8], gh[8];
#pragma unroll
        for (int i = 0; i < 8; i++) { gx[i] = 0.f; gh[i] = 0.f; }
#pragma unroll 4
        for (int e = 0; e < 64; e++) {
            float wi = w_ih[e * 192 + o];
            float wh = w_hh[e * 192 + o];
#pragma unroll
            for (int i = 0; i < 8; i++) {
                gx[i] += e_upd[i * 64 + e] * wi;
                gh[i] += e_prev[i * 64 + e] * wh;
            }
        }
        float bi = b_ih[o], bh = b_hh[o];
#pragma unroll
        for (int i = 0; i < 8; i++) {
            e_gx[i * 192 + o] = gx[i] + bi;
            e_gh[i * 192 + o] = gh[i] + bh;
        }
    }
    __syncthreads();
#pragma unroll
    for (int rep = 0; rep < 4; rep++) {
        int k = tid + rep * TPB;
        int i = k >> 6, d = k & 63, o = i * 192;
        float rx = e_gx[o + d] + e_gh[o + d];
        float zx = e_gx[o + 64 + d] + e_gh[o + 64 + d];
        float nx = e_gx[o + 128 + d];
        float nh = e_gh[o + 128 + d];
        float r = 1.f / (1.f + __expf(-rx));
        float z = 1.f / (1.f + __expf(-zx));
        float n = tanhf(nx + r * nh);
        e_new[k] = (1.f - z) * n + z * e_prev[k];
    }
    __syncthreads();

    // ---- D: ff = LN(new, g_ff)  (warp w handles slots w and w+4)
    {
        int w = tid >> 5, lane = tid & 31;
#pragma unroll
        for (int rep = 0; rep < 2; rep++) {
            int sl = w + rep * 4;
            float v0 = e_new[sl * 64 + lane], v1 = e_new[sl * 64 + 32 + lane];
            float s = v0 + v1, s2 = v0 * v0 + v1 * v1;
#pragma unroll
            for (int off = 16; off; off >>= 1) {
                s += __shfl_xor_sync(0xffffffffu, s, off);
                s2 += __shfl_xor_sync(0xffffffffu, s2, off);
            }
            float m = s * (1.f / 64.f);
            float var = s2 * (1.f / 64.f) - m * m;
            float r = rsqrtf(var + 1e-5f);
            e_ff[sl * 64 + lane] = (v0 - m) * r * g_ff[lane] + be_ff[lane];
            e_ff[sl * 64 + 32 + lane] = (v1 - m) * r * g_ff[lane + 32] + be_ff[lane + 32];
        }
    }
    __syncthreads();

    // ---- E: h1 = relu(ff @ w1 + b1)  (o = tid; 8 slot accs; full 64-deep)
    {
        int o = tid;
        float a[8];
        float binit = b1[o];
#pragma unroll
        for (int i = 0; i < 8; i++) a[i] = binit;
#pragma unroll 4
        for (int e = 0; e < 64; e++) {
            float w = w1[e * 128 + o];
#pragma unroll
            for (int i = 0; i < 8; i++) a[i] += e_ff[i * 64 + e] * w;
        }
#pragma unroll
        for (int i = 0; i < 8; i++) e_h1[i * 128 + o] = fmaxf(a[i], 0.f);
    }
    __syncthreads();

    // ---- F: slots = new + h1 @ w2 + b2  (d = tid&63; group owns 4 slots; 128-deep)
    {
        int d = tid & 63, grp = tid >> 6;
        float a0 = 0.f, a1 = 0.f, a2 = 0.f, a3 = 0.f;
#pragma unroll 8
        for (int e = 0; e < 128; e++) {
            float w = w2[e * 64 + d];
            a0 += e_h1[(4 * grp + 0) * 128 + e] * w;
            a1 += e_h1[(4 * grp + 1) * 128 + e] * w;
            a2 += e_h1[(4 * grp + 2) * 128 + e] * w;
            a3 += e_h1[(4 * grp + 3) * 128 + e] * w;
        }
        float bb = b2[d];
        float av[4] = {a0, a1, a2, a3};
#pragma unroll
        for (int s = 0; s < 4; s++) {
            int k = (4 * grp + s) * 64 + d;
            float val = e_new[k] + bb + av[s];
            g_slots[b * 512 + k] = val;
            if (last) out[b * 512 + k] = val;
            e_new[k] = val;
        }
    }
    if (last) return;
    __syncthreads();

    // ---- G: qfold
    {
        int w = tid >> 5, lane = tid & 31;
#pragma unroll
        for (int rep = 0; rep < 2; rep++) {
            int sl = w + rep * 4;
            float v0 = e_new[sl * 64 + lane], v1 = e_new[sl * 64 + 32 + lane];
            float s = v0 + v1, s2 = v0 * v0 + v1 * v1;
#pragma unroll
            for (int off = 16; off; off >>= 1) {
                s += __shfl_xor_sync(0xffffffffu, s, off);
                s2 += __shfl_xor_sync(0xffffffffu, s2, off);
            }
            float m = s * (1.f / 64.f);
            float var = s2 * (1.f / 64.f) - m * m;
            float r = rsqrtf(var + 1e-5f);
            e_ff[sl * 64 + lane] = (v0 - m) * r * g_sl[lane] + be_sl[lane];
            e_ff[sl * 64 + 32 + lane] = (v1 - m) * r * g_sl[lane + 32] + be_sl[lane + 32];
        }
    }
    __syncthreads();
    {
        int d = tid & 63, grp = tid >> 6;
        float bq0 = g_bqk[d];
        float a0 = bq0, a1 = bq0, a2 = bq0, a3 = bq0;
#pragma unroll 8
        for (int e = 0; e < 64; e++) {
            float w = g_wqk[e * 64 + d];
            a0 += e_ff[(4 * grp + 0) * 64 + e] * w;
            a1 += e_ff[(4 * grp + 1) * 64 + e] * w;
            a2 += e_ff[(4 * grp + 2) * 64 + e] * w;
            a3 += e_ff[(4 * grp + 3) * 64 + e] * w;
        }
        float av[4] = {a0, a1, a2, a3};
        float gi = g_in[d], bi = be_in[d];
#pragma unroll
        for (int s = 0; s < 4; s++) {
            int k = (4 * grp + s) * 64 + d;
            float qt = 0.125f * av[s];
            float qhv = qt * gi;
            g_qhat[b * 512 + k] = qhv;
            e_gx[k] = qhv;
            e_gh[k] = qt * bi;
        }
    }
    __syncthreads();
    {
        int w = tid >> 5, lane = tid & 31;
#pragma unroll
        for (int rep = 0; rep < 2; rep++) {
            int sl = w + rep * 4;
            float sq = e_gx[sl * 64 + lane] + e_gx[sl * 64 + lane + 32];
            float cb = e_gh[sl * 64 + lane] + e_gh[sl * 64 + lane + 32];
            float qb = e_ff[sl * 64 + lane] * g_wqbk[lane] + e_ff[sl * 64 + lane + 32] * g_wqbk[lane + 32];
#pragma unroll
            for (int off = 16; off; off >>= 1) {
                sq += __shfl_xor_sync(0xffffffffu, sq, off);
                cb += __shfl_xor_sync(0xffffffffu, cb, off);
                qb += __shfl_xor_sync(0xffffffffu, qb, off);
            }
            if (lane == 0) {
                g_sq[b * S + sl] = sq;
                g_cst[b * S + sl] = cb + 0.125f * (qb + g_bqbk[0]);
            }
        }
    }
}

// ---------------- launch ----------------
extern "C" void kernel_launch(void* const* d_in, const int* in_sizes, int n_in,
                              void* d_out, int out_size) {
    (void)in_sizes; (void)n_in; (void)out_size;
    const float* inputs = (const float*)d_in[0];
    const float* noise  = (const float*)d_in[1];
    const float* mu     = (const float*)d_in[2];
    const float* ls     = (const float*)d_in[3];
    const float* wq = (const float*)d_in[4];
    const float* bq = (const float*)d_in[5];
    const float* wk = (const float*)d_in[6];
    const float* bk = (const float*)d_in[7];
    const float* wv = (const float*)d_in[8];
    const float* bv = (const float*)d_in[9];
    const float* w_ih = (const float*)d_in[10];
    const float* b_ih = (const float*)d_in[11];
    const float* w_hh = (const float*)d_in[12];
    const float* b_hh = (const float*)d_in[13];
    const float* w1 = (const float*)d_in[14];
    const float* b1 = (const float*)d_in[15];
    const float* w2 = (const float*)d_in[16];
    const float* b2 = (const float*)d_in[17];
    const float* gin = (const float*)d_in[18];
    const float* bin = (const float*)d_in[19];
    const float* gsl = (const float*)d_in[20];
    const float* bsl = (const float*)d_in[21];
    const float* gff = (const float*)d_in[22];
    const float* bff = (const float*)d_in[23];
    float* out = (float*)d_out;

    k_pre<<<1, 256>>>(wq, bq, wk, bk);
    k_init<<<B, 256>>>(noise, mu, ls, gsl, bsl, gin, bin);
    for (int it = 0; it < 3; it++) {
        k_main<<<dim3(CHUNKS, B), TPB>>>(inputs,
                                         wv, bv, w_ih, b_ih, w_hh, b_hh,
                                         w1, b1, w2, b2,
                                         gff, bff, gsl, bsl, gin, bin,
                                         out, it == 2 ? 1 : 0);
    }
}

// round 8
// speedup vs baseline: 1.3277x; 1.3277x over previous
#include <cuda_runtime.h>
#include <math.h>

#define B 64
#define NTOK 4096
#define D 64
#define S 8
#define HID 128
#define CHUNKS 16
#define NC (NTOK / CHUNKS)   /* 256 tokens per block */
#define TILE 128
#define TPB_MAIN 128
#define XS_STRIDE 68         /* floats per token row; 272B, 16B aligned */

typedef unsigned long long u64t;

__device__ __forceinline__ u64t f2_fma(u64t a, u64t b, u64t c) {
    u64t d;
    asm("fma.rn.f32x2 %0, %1, %2, %3;" : "=l"(d) : "l"(a), "l"(b), "l"(c));
    return d;
}
__device__ __forceinline__ u64t f2_add(u64t a, u64t b) {
    u64t d;
    asm("add.rn.f32x2 %0, %1, %2;" : "=l"(d) : "l"(a), "l"(b));
    return d;
}
__device__ __forceinline__ float2 f2_unpack(u64t a) {
    float2 r;
    asm("mov.b64 {%0, %1}, %2;" : "=f"(r.x), "=f"(r.y) : "l"(a));
    return r;
}

// ---------------- device scratch ----------------
__device__ float g_slots[B * S * D];
__device__ float g_qhat[B * S * D];
__device__ float g_sq[B * S];
__device__ float g_cst[B * S];
__device__ float g_P[B * CHUNKS * S * D];
__device__ float g_Td[B * CHUNKS * 16];
__device__ float g_wqk[D * D];
__device__ float g_bqk[D];
__device__ float g_wqbk[D];
__device__ float g_bqbk[1];

// ---------------- precompute folded weight products ----------------
__global__ __launch_bounds__(256) void k_pre(const float* __restrict__ wq,
                                             const float* __restrict__ bq,
                                             const float* __restrict__ wk,
                                             const float* __restrict__ bk) {
    int t = threadIdx.x;
    for (int o = t; o < D * D; o += 256) {
        int e = o >> 6, e2 = o & 63;
        float s = 0.f;
        for (int d = 0; d < D; d++) s += wq[e * D + d] * wk[e2 * D + d];
        g_wqk[o] = s;
    }
    for (int e2 = t; e2 < D; e2 += 256) {
        float s = 0.f;
        for (int d = 0; d < D; d++) s += bq[d] * wk[e2 * D + d];
        g_bqk[e2] = s;
    }
    for (int e = t; e < D; e += 256) {
        float s = 0.f;
        for (int d = 0; d < D; d++) s += wq[e * D + d] * bk[d];
        g_wqbk[e] = s;
    }
    if (t == 0) {
        float s = 0.f;
        for (int d = 0; d < D; d++) s += bq[d] * bk[d];
        g_bqbk[0] = s;
    }
}

// ---------------- q-fold (init path) ----------------
__device__ void compute_q_from_slots(int b, const float* s_slots,
                                     const float* __restrict__ g_sl,
                                     const float* __restrict__ be_sl,
                                     const float* __restrict__ g_in,
                                     const float* __restrict__ be_in,
                                     float* s_sln, float* s_tmp) {
    int tid = threadIdx.x;
    int w = tid >> 5, lane = tid & 31;
    {
        float v0 = s_slots[w * 64 + lane];
        float v1 = s_slots[w * 64 + 32 + lane];
        float s = v0 + v1, s2 = v0 * v0 + v1 * v1;
#pragma unroll
        for (int off = 16; off; off >>= 1) {
            s += __shfl_xor_sync(0xffffffffu, s, off);
            s2 += __shfl_xor_sync(0xffffffffu, s2, off);
        }
        float m = s * (1.f / 64.f);
        float var = s2 * (1.f / 64.f) - m * m;
        float r = rsqrtf(var + 1e-5f);
        s_sln[w * 64 + lane] = (v0 - m) * r * g_sl[lane] + be_sl[lane];
        s_sln[w * 64 + 32 + lane] = (v1 - m) * r * g_sl[lane + 32] + be_sl[lane + 32];
    }
    __syncthreads();
    for (int rep = 0; rep < 2; rep++) {
        int idx = tid + rep * 256;
        int i = idx >> 6, e2 = idx & 63;
        float acc = g_bqk[e2];
#pragma unroll 8
        for (int e = 0; e < 64; e++) acc += s_sln[i * 64 + e] * g_wqk[e * 64 + e2];
        float qt = 0.125f * acc;
        float qh = qt * g_in[e2];
        g_qhat[b * S * D + idx] = qh;
        s_tmp[idx] = qh;
        s_tmp[512 + idx] = qt * be_in[e2];
    }
    __syncthreads();
    if (tid < S) {
        float sq = 0.f, cb = 0.f;
        for (int e2 = 0; e2 < 64; e2++) {
            sq += s_tmp[tid * 64 + e2];
            cb += s_tmp[512 + tid * 64 + e2];
        }
        float qb = g_bqbk[0];
        for (int e = 0; e < 64; e++) qb += s_sln[tid * 64 + e] * g_wqbk[e];
        g_sq[b * S + tid] = sq;
        g_cst[b * S + tid] = cb + 0.125f * qb;
    }
}

// ---------------- init ----------------
__global__ __launch_bounds__(256) void k_init(const float* __restrict__ noise,
                                              const float* __restrict__ mu,
                                              const float* __restrict__ ls,
                                              const float* __restrict__ g_sl,
                                              const float* __restrict__ be_sl,
                                              const float* __restrict__ g_in,
                                              const float* __restrict__ be_in) {
    __shared__ float s_slots[512];
    __shared__ float s_sln[512];
    __shared__ float s_tmp[1024];
    int b = blockIdx.x, tid = threadIdx.x;
    for (int k = tid; k < 512; k += 256) {
        int d = k & 63;
        float v = mu[d] + expf(ls[d]) * noise[b * 512 + k];
        s_slots[k] = v;
        g_slots[b * 512 + k] = v;
    }
    __syncthreads();
    compute_q_from_slots(b, s_slots, g_sl, be_sl, g_in, be_in, s_sln, s_tmp);
}

// ---------------- main streaming pass (fp32, f32x2 phase 1) ----------------
__global__ __launch_bounds__(TPB_MAIN) void k_main(const float* __restrict__ x) {
    __shared__ __align__(16) float xs[TILE * XS_STRIDE];
    __shared__ __align__(16) float attn_s[S * TILE];
    __shared__ __align__(16) float qh[S * D];
    __shared__ float sqs[S], csts[S];
    __shared__ float s_red[4][16];

    int b = blockIdx.y, c = blockIdx.x, tid = threadIdx.x;
    for (int k = tid; k < S * D; k += TPB_MAIN) qh[k] = g_qhat[b * S * D + k];
    if (tid < S) {
        sqs[tid] = g_sq[b * S + tid];
        csts[tid] = g_cst[b * S + tid];
    }

    float acc0 = 0.f, acc1 = 0.f, acc2 = 0.f, acc3 = 0.f;
    float Tl[S], dl[S];
#pragma unroll
    for (int i = 0; i < S; i++) { Tl[i] = 0.f; dl[i] = 0.f; }

    const float* xb = x + ((size_t)b * NTOK + (size_t)c * NC) * D;
    const int dd = tid & 63, ip = tid >> 6;

    for (int t = 0; t < NC / TILE; t++) {
        __syncthreads();  // protect xs reuse
        const float4* src = (const float4*)(xb + t * TILE * D);
#pragma unroll
        for (int idx = tid; idx < TILE * D / 4; idx += TPB_MAIN) {
            float4 v = src[idx];
            float* dst = &xs[(idx >> 4) * XS_STRIDE + (idx & 15) * 4];
            dst[0] = v.x; dst[1] = v.y; dst[2] = v.z; dst[3] = v.w;
        }
        __syncthreads();

        // ---- phase 1 (packed f32x2): thread owns token j = tid
        u64t dslP[S];
#pragma unroll
        for (int i = 0; i < S; i++) dslP[i] = 0ULL;
        u64t sA = 0ULL, sB = 0ULL, qA = 0ULL, qB = 0ULL;
        const ulonglong2* xr2 = (const ulonglong2*)&xs[tid * XS_STRIDE];
        const ulonglong2* qh2 = (const ulonglong2*)qh;
#pragma unroll
        for (int d4 = 0; d4 < 16; d4++) {
            ulonglong2 xp = xr2[d4];
            sA = f2_add(sA, xp.x);
            sB = f2_add(sB, xp.y);
            qA = f2_fma(xp.x, xp.x, qA);
            qB = f2_fma(xp.y, xp.y, qB);
#pragma unroll
            for (int i = 0; i < S; i++) {
                ulonglong2 qp = qh2[i * 16 + d4];
                dslP[i] = f2_fma(qp.x, xp.x, dslP[i]);
                dslP[i] = f2_fma(qp.y, xp.y, dslP[i]);
            }
        }
        float2 sfin = f2_unpack(f2_add(sA, sB));
        float2 qfin = f2_unpack(f2_add(qA, qB));
        float sum = sfin.x + sfin.y;
        float s2 = qfin.x + qfin.y;

        float m = sum * (1.f / 64.f);
        float var = s2 * (1.f / 64.f) - m * m;
        float r = rsqrtf(var + 1e-5f);
        float mx = -1e30f, dots[S];
#pragma unroll
        for (int i = 0; i < S; i++) {
            float2 dp = f2_unpack(dslP[i]);
            float dsl = dp.x + dp.y;
            dots[i] = r * (dsl - m * sqs[i]) + csts[i];
            mx = fmaxf(mx, dots[i]);
        }
        float es = 0.f, ex[S];
#pragma unroll
        for (int i = 0; i < S; i++) { ex[i] = __expf(dots[i] - mx); es += ex[i]; }
        float inv = 1.f / es;
        float rm = r * m;
#pragma unroll
        for (int i = 0; i < S; i++) {
            float ai = ex[i] * inv + 1e-8f;
            dl[i] += ai;
            Tl[i] += ai * rm;
            attn_s[i * TILE + tid] = ai * r;
        }
        __syncthreads();

        // ---- phase 2: thread owns (d=dd, slots {ip,ip+2,ip+4,ip+6})
#pragma unroll 8
        for (int j4 = 0; j4 < TILE / 4; j4++) {
            float4 a0 = ((const float4*)(attn_s + (ip + 0) * TILE))[j4];
            float4 a1 = ((const float4*)(attn_s + (ip + 2) * TILE))[j4];
            float4 a2 = ((const float4*)(attn_s + (ip + 4) * TILE))[j4];
            float4 a3 = ((const float4*)(attn_s + (ip + 6) * TILE))[j4];
            const float* xc = &xs[j4 * 4 * XS_STRIDE + dd];
            float x0 = xc[0], x1 = xc[XS_STRIDE], x2 = xc[2 * XS_STRIDE], x3 = xc[3 * XS_STRIDE];
            acc0 += a0.x * x0 + a0.y * x1 + a0.z * x2 + a0.w * x3;
            acc1 += a1.x * x0 + a1.y * x1 + a1.z * x2 + a1.w * x3;
            acc2 += a2.x * x0 + a2.y * x1 + a2.z * x2 + a2.w * x3;
            acc3 += a3.x * x0 + a3.y * x1 + a3.z * x2 + a3.w * x3;
        }
    }

    float* Pp = &g_P[(b * CHUNKS + c) * S * D];
    Pp[(ip + 0) * D + dd] = acc0;
    Pp[(ip + 2) * D + dd] = acc1;
    Pp[(ip + 4) * D + dd] = acc2;
    Pp[(ip + 6) * D + dd] = acc3;

#pragma unroll
    for (int i = 0; i < S; i++) {
#pragma unroll
        for (int off = 16; off; off >>= 1) {
            Tl[i] += __shfl_xor_sync(0xffffffffu, Tl[i], off);
            dl[i] += __shfl_xor_sync(0xffffffffu, dl[i], off);
        }
    }
    int w = tid >> 5, lane = tid & 31;
    if (lane == 0) {
#pragma unroll
        for (int i = 0; i < S; i++) { s_red[w][i] = Tl[i]; s_red[w][8 + i] = dl[i]; }
    }
    __syncthreads();
    if (tid < 16) {
        float s = s_red[0][tid] + s_red[1][tid] + s_red[2][tid] + s_red[3][tid];
        g_Td[(b * CHUNKS + c) * 16 + tid] = s;
    }
}

// ---------------- post stage: grid (2, B), 384 thr, 4 slots/block ----------------
// Weight-reuse design: threads own output column o, keep one acc per slot.
__global__ __launch_bounds__(384) void k_post(
    const float* __restrict__ wv, const float* __restrict__ bv,
    const float* __restrict__ w_ih, const float* __restrict__ b_ih,
    const float* __restrict__ w_hh, const float* __restrict__ b_hh,
    const float* __restrict__ w1, const float* __restrict__ b1,
    const float* __restrict__ w2, const float* __restrict__ b2,
    const float* __restrict__ g_ff, const float* __restrict__ be_ff,
    const float* __restrict__ g_sl, const float* __restrict__ be_sl,
    const float* __restrict__ g_in, const float* __restrict__ be_in,
    float* __restrict__ out, int last) {
    __shared__ float s_prev[256], s_num[256], s_upd[256], s_new[256], s_ff[256];
    __shared__ float s_pp[1024];
    __shared__ float s_gx[1536], s_gh[1536];   // [half][slot*192 + o]
    __shared__ float s_h1[512];
    __shared__ float s_Td[8];                  // T[0..3], den[4..7]

    int sg = blockIdx.x, b = blockIdx.y, tid = threadIdx.x;
    int i0 = sg * 4;
    int base = b * 512 + i0 * 64;

    // ---- A: prev slots + P reduce (tid<256), Td reduce (tid 256..263)
    float Pacc = 0.f;
    if (tid < 256) {
        s_prev[tid] = g_slots[base + tid];
#pragma unroll
        for (int c = 0; c < CHUNKS; c++) Pacc += g_P[(b * CHUNKS + c) * 512 + i0 * 64 + tid];
    } else if (tid < 264) {
        int l = tid - 256;
        int idx = (l < 4) ? (i0 + l) : (8 + i0 + l - 4);
        float s = 0.f;
#pragma unroll
        for (int c = 0; c < CHUNKS; c++) s += g_Td[(b * CHUNKS + c) * 16 + idx];
        s_Td[l] = s;
    }
    __syncthreads();
    if (tid < 256) {
        int sl = tid >> 6, e = tid & 63;
        s_num[tid] = g_in[e] * (Pacc - s_Td[sl]) + s_Td[4 + sl] * be_in[e];
    }
    __syncthreads();

    // ---- B: upd = (num @ wv)/den + bv   (thread owns d; 4-way e-split; 4 slot accs)
    if (tid < 256) {
        int d = tid & 63, part = tid >> 6;
        float a0 = 0.f, a1 = 0.f, a2 = 0.f, a3 = 0.f;
#pragma unroll
        for (int e4 = 0; e4 < 4; e4++) {
            int ee = part * 16 + e4 * 4;
            float4 n0 = *(const float4*)&s_num[0 * 64 + ee];
            float4 n1 = *(const float4*)&s_num[1 * 64 + ee];
            float4 n2 = *(const float4*)&s_num[2 * 64 + ee];
            float4 n3 = *(const float4*)&s_num[3 * 64 + ee];
            float w0 = wv[(ee + 0) * 64 + d], w1v = wv[(ee + 1) * 64 + d];
            float w2v = wv[(ee + 2) * 64 + d], w3 = wv[(ee + 3) * 64 + d];
            a0 += n0.x * w0 + n0.y * w1v + n0.z * w2v + n0.w * w3;
            a1 += n1.x * w0 + n1.y * w1v + n1.z * w2v + n1.w * w3;
            a2 += n2.x * w0 + n2.y * w1v + n2.z * w2v + n2.w * w3;
            a3 += n3.x * w0 + n3.y * w1v + n3.z * w2v + n3.w * w3;
        }
        s_pp[(part * 4 + 0) * 64 + d] = a0;
        s_pp[(part * 4 + 1) * 64 + d] = a1;
        s_pp[(part * 4 + 2) * 64 + d] = a2;
        s_pp[(part * 4 + 3) * 64 + d] = a3;
    }
    __syncthreads();
    if (tid < 256) {
        int sl = tid >> 6, d = tid & 63;
        float s = s_pp[sl * 64 + d] + s_pp[(4 + sl) * 64 + d] +
                  s_pp[(8 + sl) * 64 + d] + s_pp[(12 + sl) * 64 + d];
        s_upd[tid] = s / s_Td[4 + sl] + bv[d];
    }
    __syncthreads();

    // ---- C: GRU gates (thread owns o in [0,192); 2-way e-split; 4 slot accs each)
    {
        int half = (tid >= 192) ? 1 : 0;
        int o = tid - half * 192;
        float gx0 = 0.f, gx1 = 0.f, gx2 = 0.f, gx3 = 0.f;
        float gh0 = 0.f, gh1 = 0.f, gh2 = 0.f, gh3 = 0.f;
#pragma unroll
        for (int e4 = 0; e4 < 8; e4++) {
            int ee = half * 32 + e4 * 4;
            float4 u0 = *(const float4*)&s_upd[0 * 64 + ee];
            float4 u1 = *(const float4*)&s_upd[1 * 64 + ee];
            float4 u2 = *(const float4*)&s_upd[2 * 64 + ee];
            float4 u3 = *(const float4*)&s_upd[3 * 64 + ee];
            float4 p0 = *(const float4*)&s_prev[0 * 64 + ee];
            float4 p1 = *(const float4*)&s_prev[1 * 64 + ee];
            float4 p2 = *(const float4*)&s_prev[2 * 64 + ee];
            float4 p3 = *(const float4*)&s_prev[3 * 64 + ee];
            float wi0 = w_ih[(ee + 0) * 192 + o], wi1 = w_ih[(ee + 1) * 192 + o];
            float wi2 = w_ih[(ee + 2) * 192 + o], wi3 = w_ih[(ee + 3) * 192 + o];
            float wh0 = w_hh[(ee + 0) * 192 + o], wh1 = w_hh[(ee + 1) * 192 + o];
            float wh2 = w_hh[(ee + 2) * 192 + o], wh3 = w_hh[(ee + 3) * 192 + o];
            gx0 += u0.x * wi0 + u0.y * wi1 + u0.z * wi2 + u0.w * wi3;
            gx1 += u1.x * wi0 + u1.y * wi1 + u1.z * wi2 + u1.w * wi3;
            gx2 += u2.x * wi0 + u2.y * wi1 + u2.z * wi2 + u2.w * wi3;
            gx3 += u3.x * wi0 + u3.y * wi1 + u3.z * wi2 + u3.w * wi3;
            gh0 += p0.x * wh0 + p0.y * wh1 + p0.z * wh2 + p0.w * wh3;
            gh1 += p1.x * wh0 + p1.y * wh1 + p1.z * wh2 + p1.w * wh3;
            gh2 += p2.x * wh0 + p2.y * wh1 + p2.z * wh2 + p2.w * wh3;
            gh3 += p3.x * wh0 + p3.y * wh1 + p3.z * wh2 + p3.w * wh3;
        }
        if (!half) {
            float bi = b_ih[o], bh = b_hh[o];
            gx0 += bi; gx1 += bi; gx2 += bi; gx3 += bi;
            gh0 += bh; gh1 += bh; gh2 += bh; gh3 += bh;
        }
        int hb = half * 768;
        s_gx[hb + 0 * 192 + o] = gx0; s_gx[hb + 1 * 192 + o] = gx1;
        s_gx[hb + 2 * 192 + o] = gx2; s_gx[hb + 3 * 192 + o] = gx3;
        s_gh[hb + 0 * 192 + o] = gh0; s_gh[hb + 1 * 192 + o] = gh1;
        s_gh[hb + 2 * 192 + o] = gh2; s_gh[hb + 3 * 192 + o] = gh3;
    }
    __syncthreads();
    if (tid < 256) {
        int sl = tid >> 6, d = tid & 63;
        int o = sl * 192;
        float rx = s_gx[o + d] + s_gx[768 + o + d] + s_gh[o + d] + s_gh[768 + o + d];
        float zx = s_gx[o + 64 + d] + s_gx[768 + o + 64 + d] + s_gh[o + 64 + d] + s_gh[768 + o + 64 + d];
        float nx = s_gx[o + 128 + d] + s_gx[768 + o + 128 + d];
        float nh = s_gh[o + 128 + d] + s_gh[768 + o + 128 + d];
        float r = 1.f / (1.f + __expf(-rx));
        float z = 1.f / (1.f + __expf(-zx));
        float n = tanhf(nx + r * nh);
        s_new[tid] = (1.f - z) * n + z * s_prev[tid];
    }
    __syncthreads();

    // ---- D: ff = LN(new, g_ff, be_ff)  (warps 0-3, one slot each)
    if (tid < 128) {
        int w = tid >> 5, lane = tid & 31;
        float v0 = s_new[w * 64 + lane], v1 = s_new[w * 64 + 32 + lane];
        float s = v0 + v1, s2 = v0 * v0 + v1 * v1;
#pragma unroll
        for (int off = 16; off; off >>= 1) {
            s += __shfl_xor_sync(0xffffffffu, s, off);
            s2 += __shfl_xor_sync(0xffffffffu, s2, off);
        }
        float m = s * (1.f / 64.f);
        float var = s2 * (1.f / 64.f) - m * m;
        float r = rsqrtf(var + 1e-5f);
        s_ff[w * 64 + lane] = (v0 - m) * r * g_ff[lane] + be_ff[lane];
        s_ff[w * 64 + 32 + lane] = (v1 - m) * r * g_ff[lane + 32] + be_ff[lane + 32];
    }
    __syncthreads();

    // ---- E: h1 = relu(ff @ w1 + b1)  (thread owns o in [0,128); 2-way e-split)
    if (tid < 256) {
        int o = tid & 127, half = tid >> 7;
        float a0 = half ? 0.f : b1[o], a1 = 0.f, a2 = 0.f, a3 = 0.f;
        if (!half) { a1 = b1[o]; a2 = b1[o]; a3 = b1[o]; }
#pragma unroll
        for (int e4 = 0; e4 < 8; e4++) {
            int ee = half * 32 + e4 * 4;
            float4 f0 = *(const float4*)&s_ff[0 * 64 + ee];
            float4 f1 = *(const float4*)&s_ff[1 * 64 + ee];
            float4 f2 = *(const float4*)&s_ff[2 * 64 + ee];
            float4 f3 = *(const float4*)&s_ff[3 * 64 + ee];
            float w0 = w1[(ee + 0) * 128 + o], w1v = w1[(ee + 1) * 128 + o];
            float w2v = w1[(ee + 2) * 128 + o], w3 = w1[(ee + 3) * 128 + o];
            a0 += f0.x * w0 + f0.y * w1v + f0.z * w2v + f0.w * w3;
            a1 += f1.x * w0 + f1.y * w1v + f1.z * w2v + f1.w * w3;
            a2 += f2.x * w0 + f2.y * w1v + f2.z * w2v + f2.w * w3;
            a3 += f3.x * w0 + f3.y * w1v + f3.z * w2v + f3.w * w3;
        }
        s_pp[half * 512 + 0 * 128 + o] = a0;
        s_pp[half * 512 + 1 * 128 + o] = a1;
        s_pp[half * 512 + 2 * 128 + o] = a2;
        s_pp[half * 512 + 3 * 128 + o] = a3;
    }
    __syncthreads();
    for (int k = tid; k < 512; k += 384)
        s_h1[k] = fmaxf(s_pp[k] + s_pp[512 + k], 0.f);
    __syncthreads();

    // ---- F: slots = new + h1 @ w2 + b2  (thread owns d; 4-way e-split of 128)
    if (tid < 256) {
        int d = tid & 63, part = tid >> 6;
        float a0 = 0.f, a1 = 0.f, a2 = 0.f, a3 = 0.f;
#pragma unroll
        for (int e4 = 0; e4 < 8; e4++) {
            int ee = part * 32 + e4 * 4;
            float4 h0 = *(const float4*)&s_h1[0 * 128 + ee];
            float4 h1 = *(const float4*)&s_h1[1 * 128 + ee];
            float4 h2 = *(const float4*)&s_h1[2 * 128 + ee];
            float4 h3 = *(const float4*)&s_h1[3 * 128 + ee];
            float w0 = w2[(ee + 0) * 64 + d], w1v = w2[(ee + 1) * 64 + d];
            float w2v = w2[(ee + 2) * 64 + d], w3 = w2[(ee + 3) * 64 + d];
            a0 += h0.x * w0 + h0.y * w1v + h0.z * w2v + h0.w * w3;
            a1 += h1.x * w0 + h1.y * w1v + h1.z * w2v + h1.w * w3;
            a2 += h2.x * w0 + h2.y * w1v + h2.z * w2v + h2.w * w3;
            a3 += h3.x * w0 + h3.y * w1v + h3.z * w2v + h3.w * w3;
        }
        s_pp[(part * 4 + 0) * 64 + d] = a0;
        s_pp[(part * 4 + 1) * 64 + d] = a1;
        s_pp[(part * 4 + 2) * 64 + d] = a2;
        s_pp[(part * 4 + 3) * 64 + d] = a3;
    }
    __syncthreads();
    if (tid < 256) {
        int sl = tid >> 6, d = tid & 63;
        float val = s_new[tid] + b2[d] + s_pp[sl * 64 + d] + s_pp[(4 + sl) * 64 + d] +
                    s_pp[(8 + sl) * 64 + d] + s_pp[(12 + sl) * 64 + d];
        g_slots[base + tid] = val;
        if (last) out[base + tid] = val;
        s_new[tid] = val;
    }
    if (last) return;
    __syncthreads();

    // ---- G: qfold — sln = LN(val, g_sl, be_sl)
    if (tid < 128) {
        int w = tid >> 5, lane = tid & 31;
        float v0 = s_new[w * 64 + lane], v1 = s_new[w * 64 + 32 + lane];
        float s = v0 + v1, s2 = v0 * v0 + v1 * v1;
#pragma unroll
        for (int off = 16; off; off >>= 1) {
            s += __shfl_xor_sync(0xffffffffu, s, off);
            s2 += __shfl_xor_sync(0xffffffffu, s2, off);
        }
        float m = s * (1.f / 64.f);
        float var = s2 * (1.f / 64.f) - m * m;
        float r = rsqrtf(var + 1e-5f);
        s_ff[w * 64 + lane] = (v0 - m) * r * g_sl[lane] + be_sl[lane];
        s_ff[w * 64 + 32 + lane] = (v1 - m) * r * g_sl[lane + 32] + be_sl[lane + 32];
    }
    __syncthreads();

    // q~ = sln @ wqk + bqk (thread owns d; 4-way e-split)
    if (tid < 256) {
        int d = tid & 63, part = tid >> 6;
        float a0 = part ? 0.f : g_bqk[d];
        float a1 = a0, a2 = a0, a3 = a0;
#pragma unroll
        for (int e4 = 0; e4 < 4; e4++) {
            int ee = part * 16 + e4 * 4;
            float4 f0 = *(const float4*)&s_ff[0 * 64 + ee];
            float4 f1 = *(const float4*)&s_ff[1 * 64 + ee];
            float4 f2 = *(const float4*)&s_ff[2 * 64 + ee];
            float4 f3 = *(const float4*)&s_ff[3 * 64 + ee];
            float w0 = g_wqk[(ee + 0) * 64 + d], w1v = g_wqk[(ee + 1) * 64 + d];
            float w2v = g_wqk[(ee + 2) * 64 + d], w3 = g_wqk[(ee + 3) * 64 + d];
            a0 += f0.x * w0 + f0.y * w1v + f0.z * w2v + f0.w * w3;
            a1 += f1.x * w0 + f1.y * w1v + f1.z * w2v + f1.w * w3;
            a2 += f2.x * w0 + f2.y * w1v + f2.z * w2v + f2.w * w3;
            a3 += f3.x * w0 + f3.y * w1v + f3.z * w2v + f3.w * w3;
        }
        s_pp[(part * 4 + 0) * 64 + d] = a0;
        s_pp[(part * 4 + 1) * 64 + d] = a1;
        s_pp[(part * 4 + 2) * 64 + d] = a2;
        s_pp[(part * 4 + 3) * 64 + d] = a3;
    }
    __syncthreads();
    if (tid < 256) {
        int sl = tid >> 6, d = tid & 63;
        float qt = 0.125f * (s_pp[sl * 64 + d] + s_pp[(4 + sl) * 64 + d] +
                             s_pp[(8 + sl) * 64 + d] + s_pp[(12 + sl) * 64 + d]);
        float qhv = qt * g_in[d];
        g_qhat[base + tid] = qhv;
        s_gx[tid] = qhv;
        s_gh[tid] = qt * be_in[d];
    }
    __syncthreads();
    if (tid < 128) {
        int w = tid >> 5, lane = tid & 31;
        float sq = s_gx[w * 64 + lane] + s_gx[w * 64 + lane + 32];
        float cb = s_gh[w * 64 + lane] + s_gh[w * 64 + lane + 32];
        float qb = s_ff[w * 64 + lane] * g_wqbk[lane] + s_ff[w * 64 + lane + 32] * g_wqbk[lane + 32];
#pragma unroll
        for (int off = 16; off; off >>= 1) {
            sq += __shfl_xor_sync(0xffffffffu, sq, off);
            cb += __shfl_xor_sync(0xffffffffu, cb, off);
            qb += __shfl_xor_sync(0xffffffffu, qb, off);
        }
        if (lane == 0) {
            g_sq[b * S + i0 + w] = sq;
            g_cst[b * S + i0 + w] = cb + 0.125f * (qb + g_bqbk[0]);
        }
    }
}

// ---------------- launch ----------------
extern "C" void kernel_launch(void* const* d_in, const int* in_sizes, int n_in,
                              void* d_out, int out_size) {
    (void)in_sizes; (void)n_in; (void)out_size;
    const float* inputs = (const float*)d_in[0];
    const float* noise  = (const float*)d_in[1];
    const float* mu     = (const float*)d_in[2];
    const float* ls     = (const float*)d_in[3];
    const float* wq = (const float*)d_in[4];
    const float* bq = (const float*)d_in[5];
    const float* wk = (const float*)d_in[6];
    const float* bk = (const float*)d_in[7];
    const float* wv = (const float*)d_in[8];
    const float* bv = (const float*)d_in[9];
    const float* w_ih = (const float*)d_in[10];
    const float* b_ih = (const float*)d_in[11];
    const float* w_hh = (const float*)d_in[12];
    const float* b_hh = (const float*)d_in[13];
    const float* w1 = (const float*)d_in[14];
    const float* b1 = (const float*)d_in[15];
    const float* w2 = (const float*)d_in[16];
    const float* b2 = (const float*)d_in[17];
    const float* gin = (const float*)d_in[18];
    const float* bin = (const float*)d_in[19];
    const float* gsl = (const float*)d_in[20];
    const float* bsl = (const float*)d_in[21];
    const float* gff = (const float*)d_in[22];
    const float* bff = (const float*)d_in[23];
    float* out = (float*)d_out;

    k_pre<<<1, 256>>>(wq, bq, wk, bk);
    k_init<<<B, 256>>>(noise, mu, ls, gsl, bsl, gin, bin);
    for (int it = 0; it < 3; it++) {
        k_main<<<dim3(CHUNKS, B), TPB_MAIN>>>(inputs);
        k_post<<<dim3(2, B), 384>>>(wv, bv, w_ih, b_ih, w_hh, b_hh, w1, b1, w2, b2,
                                    gff, bff, gsl, bsl, gin, bin, out, it == 2 ? 1 : 0);
    }
}

// round 9
// speedup vs baseline: 1.3358x; 1.0061x over previous
#include <cuda_runtime.h>
#include <math.h>

#define B 64
#define NTOK 4096
#define D 64
#define S 8
#define HID 128
#define CHUNKS 16
#define NC (NTOK / CHUNKS)   /* 256 tokens per block */
#define TILE 128
#define TPB_MAIN 128
#define XS_STRIDE 68         /* floats per token row; 272B, 16B aligned */

typedef unsigned long long u64t;

__device__ __forceinline__ u64t f2_fma(u64t a, u64t b, u64t c) {
    u64t d;
    asm("fma.rn.f32x2 %0, %1, %2, %3;" : "=l"(d) : "l"(a), "l"(b), "l"(c));
    return d;
}
__device__ __forceinline__ u64t f2_add(u64t a, u64t b) {
    u64t d;
    asm("add.rn.f32x2 %0, %1, %2;" : "=l"(d) : "l"(a), "l"(b));
    return d;
}
__device__ __forceinline__ float2 f2_unpack(u64t a) {
    float2 r;
    asm("mov.b64 {%0, %1}, %2;" : "=f"(r.x), "=f"(r.y) : "l"(a));
    return r;
}

// ---------------- device scratch ----------------
__device__ float g_slots[B * S * D];
__device__ float g_qhat[B * S * D];
__device__ float g_sq[B * S];
__device__ float g_cst[B * S];
__device__ float g_P[B * CHUNKS * S * D];
__device__ float g_Td[B * CHUNKS * 16];
__device__ float g_wqk[D * D];
__device__ float g_bqk[D];
__device__ float g_wqbk[D];
__device__ float g_bqbk[1];

// ---------------- precompute folded weight products ----------------
__global__ __launch_bounds__(256) void k_pre(const float* __restrict__ wq,
                                             const float* __restrict__ bq,
                                             const float* __restrict__ wk,
                                             const float* __restrict__ bk) {
    int t = threadIdx.x;
    for (int o = t; o < D * D; o += 256) {
        int e = o >> 6, e2 = o & 63;
        float s = 0.f;
        for (int d = 0; d < D; d++) s += wq[e * D + d] * wk[e2 * D + d];
        g_wqk[o] = s;
    }
    for (int e2 = t; e2 < D; e2 += 256) {
        float s = 0.f;
        for (int d = 0; d < D; d++) s += bq[d] * wk[e2 * D + d];
        g_bqk[e2] = s;
    }
    for (int e = t; e < D; e += 256) {
        float s = 0.f;
        for (int d = 0; d < D; d++) s += wq[e * D + d] * bk[d];
        g_wqbk[e] = s;
    }
    if (t == 0) {
        float s = 0.f;
        for (int d = 0; d < D; d++) s += bq[d] * bk[d];
        g_bqbk[0] = s;
    }
}

// ---------------- q-fold (init path) ----------------
__device__ void compute_q_from_slots(int b, const float* s_slots,
                                     const float* __restrict__ g_sl,
                                     const float* __restrict__ be_sl,
                                     const float* __restrict__ g_in,
                                     const float* __restrict__ be_in,
                                     float* s_sln, float* s_tmp) {
    int tid = threadIdx.x;
    int w = tid >> 5, lane = tid & 31;
    {
        float v0 = s_slots[w * 64 + lane];
        float v1 = s_slots[w * 64 + 32 + lane];
        float s = v0 + v1, s2 = v0 * v0 + v1 * v1;
#pragma unroll
        for (int off = 16; off; off >>= 1) {
            s += __shfl_xor_sync(0xffffffffu, s, off);
            s2 += __shfl_xor_sync(0xffffffffu, s2, off);
        }
        float m = s * (1.f / 64.f);
        float var = s2 * (1.f / 64.f) - m * m;
        float r = rsqrtf(var + 1e-5f);
        s_sln[w * 64 + lane] = (v0 - m) * r * g_sl[lane] + be_sl[lane];
        s_sln[w * 64 + 32 + lane] = (v1 - m) * r * g_sl[lane + 32] + be_sl[lane + 32];
    }
    __syncthreads();
    for (int rep = 0; rep < 2; rep++) {
        int idx = tid + rep * 256;
        int i = idx >> 6, e2 = idx & 63;
        float acc = g_bqk[e2];
#pragma unroll 8
        for (int e = 0; e < 64; e++) acc += s_sln[i * 64 + e] * g_wqk[e * 64 + e2];
        float qt = 0.125f * acc;
        float qh = qt * g_in[e2];
        g_qhat[b * S * D + idx] = qh;
        s_tmp[idx] = qh;
        s_tmp[512 + idx] = qt * be_in[e2];
    }
    __syncthreads();
    if (tid < S) {
        float sq = 0.f, cb = 0.f;
        for (int e2 = 0; e2 < 64; e2++) {
            sq += s_tmp[tid * 64 + e2];
            cb += s_tmp[512 + tid * 64 + e2];
        }
        float qb = g_bqbk[0];
        for (int e = 0; e < 64; e++) qb += s_sln[tid * 64 + e] * g_wqbk[e];
        g_sq[b * S + tid] = sq;
        g_cst[b * S + tid] = cb + 0.125f * qb;
    }
}

// ---------------- init ----------------
__global__ __launch_bounds__(256) void k_init(const float* __restrict__ noise,
                                              const float* __restrict__ mu,
                                              const float* __restrict__ ls,
                                              const float* __restrict__ g_sl,
                                              const float* __restrict__ be_sl,
                                              const float* __restrict__ g_in,
                                              const float* __restrict__ be_in) {
    __shared__ float s_slots[512];
    __shared__ float s_sln[512];
    __shared__ float s_tmp[1024];
    int b = blockIdx.x, tid = threadIdx.x;
    for (int k = tid; k < 512; k += 256) {
        int d = k & 63;
        float v = mu[d] + expf(ls[d]) * noise[b * 512 + k];
        s_slots[k] = v;
        g_slots[b * 512 + k] = v;
    }
    __syncthreads();
    compute_q_from_slots(b, s_slots, g_sl, be_sl, g_in, be_in, s_sln, s_tmp);
}

// ---------------- main streaming pass (fp32, f32x2 phase 1) ----------------
__global__ __launch_bounds__(TPB_MAIN) void k_main(const float* __restrict__ x) {
    __shared__ __align__(16) float xs[TILE * XS_STRIDE];
    __shared__ __align__(16) float attn_s[S * TILE];
    __shared__ __align__(16) float qh[S * D];
    __shared__ float sqs[S], csts[S];
    __shared__ float s_red[4][16];

    int b = blockIdx.y, c = blockIdx.x, tid = threadIdx.x;
    for (int k = tid; k < S * D; k += TPB_MAIN) qh[k] = g_qhat[b * S * D + k];
    if (tid < S) {
        sqs[tid] = g_sq[b * S + tid];
        csts[tid] = g_cst[b * S + tid];
    }

    float acc0 = 0.f, acc1 = 0.f, acc2 = 0.f, acc3 = 0.f;
    float Tl[S], dl[S];
#pragma unroll
    for (int i = 0; i < S; i++) { Tl[i] = 0.f; dl[i] = 0.f; }

    const float* xb = x + ((size_t)b * NTOK + (size_t)c * NC) * D;
    const int dd = tid & 63, ip = tid >> 6;

    for (int t = 0; t < NC / TILE; t++) {
        __syncthreads();  // protect xs reuse
        const float4* src = (const float4*)(xb + t * TILE * D);
#pragma unroll
        for (int idx = tid; idx < TILE * D / 4; idx += TPB_MAIN) {
            float4 v = src[idx];
            float* dst = &xs[(idx >> 4) * XS_STRIDE + (idx & 15) * 4];
            dst[0] = v.x; dst[1] = v.y; dst[2] = v.z; dst[3] = v.w;
        }
        __syncthreads();

        // ---- phase 1 (packed f32x2): thread owns token j = tid
        u64t dslP[S];
#pragma unroll
        for (int i = 0; i < S; i++) dslP[i] = 0ULL;
        u64t sA = 0ULL, sB = 0ULL, qA = 0ULL, qB = 0ULL;
        const ulonglong2* xr2 = (const ulonglong2*)&xs[tid * XS_STRIDE];
        const ulonglong2* qh2 = (const ulonglong2*)qh;
#pragma unroll
        for (int d4 = 0; d4 < 16; d4++) {
            ulonglong2 xp = xr2[d4];
            sA = f2_add(sA, xp.x);
            sB = f2_add(sB, xp.y);
            qA = f2_fma(xp.x, xp.x, qA);
            qB = f2_fma(xp.y, xp.y, qB);
#pragma unroll
            for (int i = 0; i < S; i++) {
                ulonglong2 qp = qh2[i * 16 + d4];
                dslP[i] = f2_fma(qp.x, xp.x, dslP[i]);
                dslP[i] = f2_fma(qp.y, xp.y, dslP[i]);
            }
        }
        float2 sfin = f2_unpack(f2_add(sA, sB));
        float2 qfin = f2_unpack(f2_add(qA, qB));
        float sum = sfin.x + sfin.y;
        float s2 = qfin.x + qfin.y;

        float m = sum * (1.f / 64.f);
        float var = s2 * (1.f / 64.f) - m * m;
        float r = rsqrtf(var + 1e-5f);
        float mx = -1e30f, dots[S];
#pragma unroll
        for (int i = 0; i < S; i++) {
            float2 dp = f2_unpack(dslP[i]);
            float dsl = dp.x + dp.y;
            dots[i] = r * (dsl - m * sqs[i]) + csts[i];
            mx = fmaxf(mx, dots[i]);
        }
        float es = 0.f, ex[S];
#pragma unroll
        for (int i = 0; i < S; i++) { ex[i] = __expf(dots[i] - mx); es += ex[i]; }
        float inv = 1.f / es;
        float rm = r * m;
#pragma unroll
        for (int i = 0; i < S; i++) {
            float ai = ex[i] * inv + 1e-8f;
            dl[i] += ai;
            Tl[i] += ai * rm;
            attn_s[i * TILE + tid] = ai * r;
        }
        __syncthreads();

        // ---- phase 2: thread owns (d=dd, slots {ip,ip+2,ip+4,ip+6})
#pragma unroll 8
        for (int j4 = 0; j4 < TILE / 4; j4++) {
            float4 a0 = ((const float4*)(attn_s + (ip + 0) * TILE))[j4];
            float4 a1 = ((const float4*)(attn_s + (ip + 2) * TILE))[j4];
            float4 a2 = ((const float4*)(attn_s + (ip + 4) * TILE))[j4];
            float4 a3 = ((const float4*)(attn_s + (ip + 6) * TILE))[j4];
            const float* xc = &xs[j4 * 4 * XS_STRIDE + dd];
            float x0 = xc[0], x1 = xc[XS_STRIDE], x2 = xc[2 * XS_STRIDE], x3 = xc[3 * XS_STRIDE];
            acc0 += a0.x * x0 + a0.y * x1 + a0.z * x2 + a0.w * x3;
            acc1 += a1.x * x0 + a1.y * x1 + a1.z * x2 + a1.w * x3;
            acc2 += a2.x * x0 + a2.y * x1 + a2.z * x2 + a2.w * x3;
            acc3 += a3.x * x0 + a3.y * x1 + a3.z * x2 + a3.w * x3;
        }
    }

    float* Pp = &g_P[(b * CHUNKS + c) * S * D];
    Pp[(ip + 0) * D + dd] = acc0;
    Pp[(ip + 2) * D + dd] = acc1;
    Pp[(ip + 4) * D + dd] = acc2;
    Pp[(ip + 6) * D + dd] = acc3;

#pragma unroll
    for (int i = 0; i < S; i++) {
#pragma unroll
        for (int off = 16; off; off >>= 1) {
            Tl[i] += __shfl_xor_sync(0xffffffffu, Tl[i], off);
            dl[i] += __shfl_xor_sync(0xffffffffu, dl[i], off);
        }
    }
    int w = tid >> 5, lane = tid & 31;
    if (lane == 0) {
#pragma unroll
        for (int i = 0; i < S; i++) { s_red[w][i] = Tl[i]; s_red[w][8 + i] = dl[i]; }
    }
    __syncthreads();
    if (tid < 16) {
        float s = s_red[0][tid] + s_red[1][tid] + s_red[2][tid] + s_red[3][tid];
        g_Td[(b * CHUNKS + c) * 16 + tid] = s;
    }
}

// ---------------- post stage: grid (2, B), 384 thr, 4 slots/block ----------------
// Weight-reuse design: threads own output column o, keep one acc per slot.
__global__ __launch_bounds__(384) void k_post(
    const float* __restrict__ wv, const float* __restrict__ bv,
    const float* __restrict__ w_ih, const float* __restrict__ b_ih,
    const float* __restrict__ w_hh, const float* __restrict__ b_hh,
    const float* __restrict__ w1, const float* __restrict__ b1,
    const float* __restrict__ w2, const float* __restrict__ b2,
    const float* __restrict__ g_ff, const float* __restrict__ be_ff,
    const float* __restrict__ g_sl, const float* __restrict__ be_sl,
    const float* __restrict__ g_in, const float* __restrict__ be_in,
    float* __restrict__ out, int last) {
    __shared__ float s_prev[256], s_num[256], s_upd[256], s_new[256], s_ff[256];
    __shared__ float s_pp[1024];
    __shared__ float s_gx[1536], s_gh[1536];   // [half][slot*192 + o]
    __shared__ float s_h1[512];
    __shared__ float s_Td[8];                  // T[0..3], den[4..7]

    int sg = blockIdx.x, b = blockIdx.y, tid = threadIdx.x;
    int i0 = sg * 4;
    int base = b * 512 + i0 * 64;

    // ---- A: prev slots + P reduce (tid<256), Td reduce (tid 256..263)
    float Pacc = 0.f;
    if (tid < 256) {
        s_prev[tid] = g_slots[base + tid];
#pragma unroll
        for (int c = 0; c < CHUNKS; c++) Pacc += g_P[(b * CHUNKS + c) * 512 + i0 * 64 + tid];
    } else if (tid < 264) {
        int l = tid - 256;
        int idx = (l < 4) ? (i0 + l) : (8 + i0 + l - 4);
        float s = 0.f;
#pragma unroll
        for (int c = 0; c < CHUNKS; c++) s += g_Td[(b * CHUNKS + c) * 16 + idx];
        s_Td[l] = s;
    }
    __syncthreads();
    if (tid < 256) {
        int sl = tid >> 6, e = tid & 63;
        s_num[tid] = g_in[e] * (Pacc - s_Td[sl]) + s_Td[4 + sl] * be_in[e];
    }
    __syncthreads();

    // ---- B: upd = (num @ wv)/den + bv   (thread owns d; 4-way e-split; 4 slot accs)
    if (tid < 256) {
        int d = tid & 63, part = tid >> 6;
        float a0 = 0.f, a1 = 0.f, a2 = 0.f, a3 = 0.f;
#pragma unroll
        for (int e4 = 0; e4 < 4; e4++) {
            int ee = part * 16 + e4 * 4;
            float4 n0 = *(const float4*)&s_num[0 * 64 + ee];
            float4 n1 = *(const float4*)&s_num[1 * 64 + ee];
            float4 n2 = *(const float4*)&s_num[2 * 64 + ee];
            float4 n3 = *(const float4*)&s_num[3 * 64 + ee];
            float w0 = wv[(ee + 0) * 64 + d], w1v = wv[(ee + 1) * 64 + d];
            float w2v = wv[(ee + 2) * 64 + d], w3 = wv[(ee + 3) * 64 + d];
            a0 += n0.x * w0 + n0.y * w1v + n0.z * w2v + n0.w * w3;
            a1 += n1.x * w0 + n1.y * w1v + n1.z * w2v + n1.w * w3;
            a2 += n2.x * w0 + n2.y * w1v + n2.z * w2v + n2.w * w3;
            a3 += n3.x * w0 + n3.y * w1v + n3.z * w2v + n3.w * w3;
        }
        s_pp[(part * 4 + 0) * 64 + d] = a0;
        s_pp[(part * 4 + 1) * 64 + d] = a1;
        s_pp[(part * 4 + 2) * 64 + d] = a2;
        s_pp[(part * 4 + 3) * 64 + d] = a3;
    }
    __syncthreads();
    if (tid < 256) {
        int sl = tid >> 6, d = tid & 63;
        float s = s_pp[sl * 64 + d] + s_pp[(4 + sl) * 64 + d] +
                  s_pp[(8 + sl) * 64 + d] + s_pp[(12 + sl) * 64 + d];
        s_upd[tid] = s / s_Td[4 + sl] + bv[d];
    }
    __syncthreads();

    // ---- C: GRU gates (thread owns o in [0,192); 2-way e-split; 4 slot accs each)
    {
        int half = (tid >= 192) ? 1 : 0;
        int o = tid - half * 192;
        float gx0 = 0.f, gx1 = 0.f, gx2 = 0.f, gx3 = 0.f;
        float gh0 = 0.f, gh1 = 0.f, gh2 = 0.f, gh3 = 0.f;
#pragma unroll
        for (int e4 = 0; e4 < 8; e4++) {
            int ee = half * 32 + e4 * 4;
            float4 u0 = *(const float4*)&s_upd[0 * 64 + ee];
            float4 u1 = *(const float4*)&s_upd[1 * 64 + ee];
            float4 u2 = *(const float4*)&s_upd[2 * 64 + ee];
            float4 u3 = *(const float4*)&s_upd[3 * 64 + ee];
            float4 p0 = *(const float4*)&s_prev[0 * 64 + ee];
            float4 p1 = *(const float4*)&s_prev[1 * 64 + ee];
            float4 p2 = *(const float4*)&s_prev[2 * 64 + ee];
            float4 p3 = *(const float4*)&s_prev[3 * 64 + ee];
            float wi0 = w_ih[(ee + 0) * 192 + o], wi1 = w_ih[(ee + 1) * 192 + o];
            float wi2 = w_ih[(ee + 2) * 192 + o], wi3 = w_ih[(ee + 3) * 192 + o];
            float wh0 = w_hh[(ee + 0) * 192 + o], wh1 = w_hh[(ee + 1) * 192 + o];
            float wh2 = w_hh[(ee + 2) * 192 + o], wh3 = w_hh[(ee + 3) * 192 + o];
            gx0 += u0.x * wi0 + u0.y * wi1 + u0.z * wi2 + u0.w * wi3;
            gx1 += u1.x * wi0 + u1.y * wi1 + u1.z * wi2 + u1.w * wi3;
            gx2 += u2.x * wi0 + u2.y * wi1 + u2.z * wi2 + u2.w * wi3;
            gx3 += u3.x * wi0 + u3.y * wi1 + u3.z * wi2 + u3.w * wi3;
            gh0 += p0.x * wh0 + p0.y * wh1 + p0.z * wh2 + p0.w * wh3;
            gh1 += p1.x * wh0 + p1.y * wh1 + p1.z * wh2 + p1.w * wh3;
            gh2 += p2.x * wh0 + p2.y * wh1 + p2.z * wh2 + p2.w * wh3;
            gh3 += p3.x * wh0 + p3.y * wh1 + p3.z * wh2 + p3.w * wh3;
        }
        if (!half) {
            float bi = b_ih[o], bh = b_hh[o];
            gx0 += bi; gx1 += bi; gx2 += bi; gx3 += bi;
            gh0 += bh; gh1 += bh; gh2 += bh; gh3 += bh;
        }
        int hb = half * 768;
        s_gx[hb + 0 * 192 + o] = gx0; s_gx[hb + 1 * 192 + o] = gx1;
        s_gx[hb + 2 * 192 + o] = gx2; s_gx[hb + 3 * 192 + o] = gx3;
        s_gh[hb + 0 * 192 + o] = gh0; s_gh[hb + 1 * 192 + o] = gh1;
        s_gh[hb + 2 * 192 + o] = gh2; s_gh[hb + 3 * 192 + o] = gh3;
    }
    __syncthreads();
    if (tid < 256) {
        int sl = tid >> 6, d = tid & 63;
        int o = sl * 192;
        float rx = s_gx[o + d] + s_gx[768 + o + d] + s_gh[o + d] + s_gh[768 + o + d];
        float zx = s_gx[o + 64 + d] + s_gx[768 + o + 64 + d] + s_gh[o + 64 + d] + s_gh[768 + o + 64 + d];
        float nx = s_gx[o + 128 + d] + s_gx[768 + o + 128 + d];
        float nh = s_gh[o + 128 + d] + s_gh[768 + o + 128 + d];
        float r = 1.f / (1.f + __expf(-rx));
        float z = 1.f / (1.f + __expf(-zx));
        float n = tanhf(nx + r * nh);
        s_new[tid] = (1.f - z) * n + z * s_prev[tid];
    }
    __syncthreads();

    // ---- D: ff = LN(new, g_ff, be_ff)  (warps 0-3, one slot each)
    if (tid < 128) {
        int w = tid >> 5, lane = tid & 31;
        float v0 = s_new[w * 64 + lane], v1 = s_new[w * 64 + 32 + lane];
        float s = v0 + v1, s2 = v0 * v0 + v1 * v1;
#pragma unroll
        for (int off = 16; off; off >>= 1) {
            s += __shfl_xor_sync(0xffffffffu, s, off);
            s2 += __shfl_xor_sync(0xffffffffu, s2, off);
        }
        float m = s * (1.f / 64.f);
        float var = s2 * (1.f / 64.f) - m * m;
        float r = rsqrtf(var + 1e-5f);
        s_ff[w * 64 + lane] = (v0 - m) * r * g_ff[lane] + be_ff[lane];
        s_ff[w * 64 + 32 + lane] = (v1 - m) * r * g_ff[lane + 32] + be_ff[lane + 32];
    }
    __syncthreads();

    // ---- E: h1 = relu(ff @ w1 + b1)  (thread owns o in [0,128); 2-way e-split)
    if (tid < 256) {
        int o = tid & 127, half = tid >> 7;
        float a0 = half ? 0.f : b1[o], a1 = 0.f, a2 = 0.f, a3 = 0.f;
        if (!half) { a1 = b1[o]; a2 = b1[o]; a3 = b1[o]; }
#pragma unroll
        for (int e4 = 0; e4 < 8; e4++) {
            int ee = half * 32 + e4 * 4;
            float4 f0 = *(const float4*)&s_ff[0 * 64 + ee];
            float4 f1 = *(const float4*)&s_ff[1 * 64 + ee];
            float4 f2 = *(const float4*)&s_ff[2 * 64 + ee];
            float4 f3 = *(const float4*)&s_ff[3 * 64 + ee];
            float w0 = w1[(ee + 0) * 128 + o], w1v = w1[(ee + 1) * 128 + o];
            float w2v = w1[(ee + 2) * 128 + o], w3 = w1[(ee + 3) * 128 + o];
            a0 += f0.x * w0 + f0.y * w1v + f0.z * w2v + f0.w * w3;
            a1 += f1.x * w0 + f1.y * w1v + f1.z * w2v + f1.w * w3;
            a2 += f2.x * w0 + f2.y * w1v + f2.z * w2v + f2.w * w3;
            a3 += f3.x * w0 + f3.y * w1v + f3.z * w2v + f3.w * w3;
        }
        s_pp[half * 512 + 0 * 128 + o] = a0;
        s_pp[half * 512 + 1 * 128 + o] = a1;
        s_pp[half * 512 + 2 * 128 + o] = a2;
        s_pp[half * 512 + 3 * 128 + o] = a3;
    }
    __syncthreads();
    for (int k = tid; k < 512; k += 384)
        s_h1[k] = fmaxf(s_pp[k] + s_pp[512 + k], 0.f);
    __syncthreads();

    // ---- F: slots = new + h1 @ w2 + b2  (thread owns d; 4-way e-split of 128)
    if (tid < 256) {
        int d = tid & 63, part = tid >> 6;
        float a0 = 0.f, a1 = 0.f, a2 = 0.f, a3 = 0.f;
#pragma unroll
        for (int e4 = 0; e4 < 8; e4++) {
            int ee = part * 32 + e4 * 4;
            float4 h0 = *(const float4*)&s_h1[0 * 128 + ee];
            float4 h1 = *(const float4*)&s_h1[1 * 128 + ee];
            float4 h2 = *(const float4*)&s_h1[2 * 128 + ee];
            float4 h3 = *(const float4*)&s_h1[3 * 128 + ee];
            float w0 = w2[(ee + 0) * 64 + d], w1v = w2[(ee + 1) * 64 + d];
            float w2v = w2[(ee + 2) * 64 + d], w3 = w2[(ee + 3) * 64 + d];
            a0 += h0.x * w0 + h0.y * w1v + h0.z * w2v + h0.w * w3;
            a1 += h1.x * w0 + h1.y * w1v + h1.z * w2v + h1.w * w3;
            a2 += h2.x * w0 + h2.y * w1v + h2.z * w2v + h2.w * w3;
            a3 += h3.x * w0 + h3.y * w1v + h3.z * w2v + h3.w * w3;
        }
        s_pp[(part * 4 + 0) * 64 + d] = a0;
        s_pp[(part * 4 + 1) * 64 + d] = a1;
        s_pp[(part * 4 + 2) * 64 + d] = a2;
        s_pp[(part * 4 + 3) * 64 + d] = a3;
    }
    __syncthreads();
    if (tid < 256) {
        int sl = tid >> 6, d = tid & 63;
        float val = s_new[tid] + b2[d] + s_pp[sl * 64 + d] + s_pp[(4 + sl) * 64 + d] +
                    s_pp[(8 + sl) * 64 + d] + s_pp[(12 + sl) * 64 + d];
        g_slots[base + tid] = val;
        if (last) out[base + tid] = val;
        s_new[tid] = val;
    }
    if (last) return;
    __syncthreads();

    // ---- G: qfold — sln = LN(val, g_sl, be_sl)
    if (tid < 128) {
        int w = tid >> 5, lane = tid & 31;
        float v0 = s_new[w * 64 + lane], v1 = s_new[w * 64 + 32 + lane];
        float s = v0 + v1, s2 = v0 * v0 + v1 * v1;
#pragma unroll
        for (int off = 16; off; off >>= 1) {
            s += __shfl_xor_sync(0xffffffffu, s, off);
            s2 += __shfl_xor_sync(0xffffffffu, s2, off);
        }
        float m = s * (1.f / 64.f);
        float var = s2 * (1.f / 64.f) - m * m;
        float r = rsqrtf(var + 1e-5f);
        s_ff[w * 64 + lane] = (v0 - m) * r * g_sl[lane] + be_sl[lane];
        s_ff[w * 64 + 32 + lane] = (v1 - m) * r * g_sl[lane + 32] + be_sl[lane + 32];
    }
    __syncthreads();

    // q~ = sln @ wqk + bqk (thread owns d; 4-way e-split)
    if (tid < 256) {
        int d = tid & 63, part = tid >> 6;
        float a0 = part ? 0.f : g_bqk[d];
        float a1 = a0, a2 = a0, a3 = a0;
#pragma unroll
        for (int e4 = 0; e4 < 4; e4++) {
            int ee = part * 16 + e4 * 4;
            float4 f0 = *(const float4*)&s_ff[0 * 64 + ee];
            float4 f1 = *(const float4*)&s_ff[1 * 64 + ee];
            float4 f2 = *(const float4*)&s_ff[2 * 64 + ee];
            float4 f3 = *(const float4*)&s_ff[3 * 64 + ee];
            float w0 = g_wqk[(ee + 0) * 64 + d], w1v = g_wqk[(ee + 1) * 64 + d];
            float w2v = g_wqk[(ee + 2) * 64 + d], w3 = g_wqk[(ee + 3) * 64 + d];
            a0 += f0.x * w0 + f0.y * w1v + f0.z * w2v + f0.w * w3;
            a1 += f1.x * w0 + f1.y * w1v + f1.z * w2v + f1.w * w3;
            a2 += f2.x * w0 + f2.y * w1v + f2.z * w2v + f2.w * w3;
            a3 += f3.x * w0 + f3.y * w1v + f3.z * w2v + f3.w * w3;
        }
        s_pp[(part * 4 + 0) * 64 + d] = a0;
        s_pp[(part * 4 + 1) * 64 + d] = a1;
        s_pp[(part * 4 + 2) * 64 + d] = a2;
        s_pp[(part * 4 + 3) * 64 + d] = a3;
    }
    __syncthreads();
    if (tid < 256) {
        int sl = tid >> 6, d = tid & 63;
        float qt = 0.125f * (s_pp[sl * 64 + d] + s_pp[(4 + sl) * 64 + d] +
                             s_pp[(8 + sl) * 64 + d] + s_pp[(12 + sl) * 64 + d]);
        float qhv = qt * g_in[d];
        g_qhat[base + tid] = qhv;
        s_gx[tid] = qhv;
        s_gh[tid] = qt * be_in[d];
    }
    __syncthreads();
    if (tid < 128) {
        int w = tid >> 5, lane = tid & 31;
        float sq = s_gx[w * 64 + lane] + s_gx[w * 64 + lane + 32];
        float cb = s_gh[w * 64 + lane] + s_gh[w * 64 + lane + 32];
        float qb = s_ff[w * 64 + lane] * g_wqbk[lane] + s_ff[w * 64 + lane + 32] * g_wqbk[lane + 32];
#pragma unroll
        for (int off = 16; off; off >>= 1) {
            sq += __shfl_xor_sync(0xffffffffu, sq, off);
            cb += __shfl_xor_sync(0xffffffffu, cb, off);
            qb += __shfl_xor_sync(0xffffffffu, qb, off);
        }
        if (lane == 0) {
            g_sq[b * S + i0 + w] = sq;
            g_cst[b * S + i0 + w] = cb + 0.125f * (qb + g_bqbk[0]);
        }
    }
}

// ---------------- launch ----------------
extern "C" void kernel_launch(void* const* d_in, const int* in_sizes, int n_in,
                              void* d_out, int out_size) {
    (void)in_sizes; (void)n_in; (void)out_size;
    const float* inputs = (const float*)d_in[0];
    const float* noise  = (const float*)d_in[1];
    const float* mu     = (const float*)d_in[2];
    const float* ls     = (const float*)d_in[3];
    const float* wq = (const float*)d_in[4];
    const float* bq = (const float*)d_in[5];
    const float* wk = (const float*)d_in[6];
    const float* bk = (const float*)d_in[7];
    const float* wv = (const float*)d_in[8];
    const float* bv = (const float*)d_in[9];
    const float* w_ih = (const float*)d_in[10];
    const float* b_ih = (const float*)d_in[11];
    const float* w_hh = (const float*)d_in[12];
    const float* b_hh = (const float*)d_in[13];
    const float* w1 = (const float*)d_in[14];
    const float* b1 = (const float*)d_in[15];
    const float* w2 = (const float*)d_in[16];
    const float* b2 = (const float*)d_in[17];
    const float* gin = (const float*)d_in[18];
    const float* bin = (const float*)d_in[19];
    const float* gsl = (const float*)d_in[20];
    const float* bsl = (const float*)d_in[21];
    const float* gff = (const float*)d_in[22];
    const float* bff = (const float*)d_in[23];
    float* out = (float*)d_out;

    k_pre<<<1, 256>>>(wq, bq, wk, bk);
    k_init<<<B, 256>>>(noise, mu, ls, gsl, bsl, gin, bin);
    for (int it = 0; it < 3; it++) {
        k_main<<<dim3(CHUNKS, B), TPB_MAIN>>>(inputs);
        k_post<<<dim3(2, B), 384>>>(wv, bv, w_ih, b_ih, w_hh, b_hh, w1, b1, w2, b2,
                                    gff, bff, gsl, bsl, gin, bin, out, it == 2 ? 1 : 0);
    }
}